// round 14
// baseline (speedup 1.0000x reference)
#include <cuda_runtime.h>
#include <cuda_fp16.h>
#include <cstdint>

// ============================================================================
// MotherCubeConv: y[n] = concat(x[n], x[nbr0..3(n)]) @ W^T + b
//   N=200000, F_in=128, fan_in=640, F_out=128.
// fp16 mma.sync. R14: SINGLE fused persistent kernel (grid=148):
//   phase A: per-CTA convert own tiles' x rows -> g_x16, convert W fp32->fp16
//            straight into SMEM, detect nbr dtype, stage bias;
//   software grid barrier (all 148 CTAs co-resident; monotone counter is
//   graph-replay safe);
//   phase B: R13 GEMM loop (one barrier/slot, W resident, A double-buffered).
// ============================================================================

#define NSLOT 5
#define MAX_ROWS 200704
#define GRID_CTAS 148

// ---- scratch (__device__ globals; no allocation allowed) -------------------
__device__ uint4    g_x16[(size_t)MAX_ROWS * 16];  // fp16 image of x (51.4MB)
__device__ unsigned g_ctr;                          // grid-barrier counter

// ---- helpers ----------------------------------------------------------------
__device__ __forceinline__ uint32_t smem_u32(const void* p) {
    uint32_t a;
    asm("{ .reg .u64 t; cvta.to.shared.u64 t, %1; cvt.u32.u64 %0, t; }"
        : "=r"(a) : "l"(p));
    return a;
}

__device__ __forceinline__ void ldsm_x4(uint32_t* r, uint32_t addr) {
    asm volatile("ldmatrix.sync.aligned.m8n8.x4.shared.b16 {%0,%1,%2,%3}, [%4];"
                 : "=r"(r[0]), "=r"(r[1]), "=r"(r[2]), "=r"(r[3]) : "r"(addr));
}

__device__ __forceinline__ void mma16816(float* d, const uint32_t* a,
                                         const uint32_t* b) {
    asm volatile(
        "mma.sync.aligned.m16n8k16.row.col.f32.f16.f16.f32 "
        "{%0,%1,%2,%3}, {%4,%5,%6,%7}, {%8,%9}, {%0,%1,%2,%3};"
        : "+f"(d[0]), "+f"(d[1]), "+f"(d[2]), "+f"(d[3])
        : "r"(a[0]), "r"(a[1]), "r"(a[2]), "r"(a[3]), "r"(b[0]), "r"(b[1]));
}

#define CP_ASYNC16(dst, src) \
    asm volatile("cp.async.cg.shared.global [%0], [%1], 16;" \
                 :: "r"(dst), "l"(src) : "memory")
#define CP_COMMIT() asm volatile("cp.async.commit_group;" ::: "memory")

// Swizzled byte offset: 256B row stride (16 groups of 16B), group XOR row&7.
__device__ __forceinline__ uint32_t tile_off(int row, int k) {
    uint32_t g = (uint32_t)(k >> 3);
    return (uint32_t)row * 256u + (((g ^ (uint32_t)(row & 7)) << 4)) +
           (uint32_t)(k & 7) * 2u;
}

// ---- SMEM layout --------------------------------------------------------------
static constexpr uint32_t OFF_BIAS = 0;        // 512B (128 f32)
static constexpr uint32_t OFF_FLAG = 512;      // int: is64
static constexpr uint32_t OFF_W    = 1024;     // 5 x 32KB (resident)
static constexpr uint32_t OFF_A    = 164864;   // 2 x 32KB
static constexpr uint32_t SMEM_BYTES = 230400;

__global__ void __launch_bounds__(512, 1)
mcconv_kernel(const float* __restrict__ x, const void* __restrict__ nbr_raw,
              const float* __restrict__ Wg, const float* __restrict__ bias_g,
              float* __restrict__ out, int N) {
    extern __shared__ char smem[];
    const uint32_t sb = smem_u32(smem);
    const int tid = threadIdx.x;
    const int wid = tid >> 5;
    const int lid = tid & 31;
    const int bid = blockIdx.x;
    const int ntiles  = (N + 127) >> 7;
    const int ngroups = N * 16;            // uint4 groups of x (8 fp32 each)

    // ======================= PHASE A: preparation =============================
    if (tid < 128) ((float*)(smem + OFF_BIAS))[tid] = bias_g[tid];
    if (tid == 0) {
        // detect neighbors dtype (int64 vs silently-downcast int32):
        // int64 values < 2^31 => every high word is 0
        const int* w = (const int*)nbr_raw;
        int all0 = 1;
        for (int i = 0; i < 64; i++)
            if (w[2 * i + 1] != 0) { all0 = 0; break; }
        *(int*)(smem + OFF_FLAG) = all0;
    }

    // convert this CTA's own tiles' x rows -> g_x16 (covers all rows once)
    for (int t = bid; t < ntiles; t += GRID_CTAS) {
        const int gbase = t * 2048;        // 128 rows x 16 groups
        #pragma unroll 4
        for (int g = tid; g < 2048; g += 512) {
            const int gi = gbase + g;
            if (gi < ngroups) {
                const float4* s = (const float4*)x + (size_t)gi * 2;
                float4 a = s[0], b = s[1];
                __half2 h0 = __floats2half2_rn(a.x, a.y);
                __half2 h1 = __floats2half2_rn(a.z, a.w);
                __half2 h2 = __floats2half2_rn(b.x, b.y);
                __half2 h3 = __floats2half2_rn(b.z, b.w);
                uint4 u;
                u.x = *(uint32_t*)&h0; u.y = *(uint32_t*)&h1;
                u.z = *(uint32_t*)&h2; u.w = *(uint32_t*)&h3;
                g_x16[gi] = u;
            }
        }
    }

    // convert W fp32 -> fp16 straight into resident SMEM (swizzled)
    for (int i = tid; i < NSLOT * 128 * 64; i += 512) {
        const int cp = i & 63;
        const int f  = (i >> 6) & 127;
        const int j  = i >> 13;
        float2 w = *(const float2*)(Wg + f * 640 + j * 128 + 2 * cp);
        __half2 h = __floats2half2_rn(w.x, w.y);
        *(uint32_t*)(smem + OFF_W + (uint32_t)j * 32768u + tile_off(f, 2 * cp)) =
            *(uint32_t*)&h;
    }

    __threadfence();      // flush x16 STGs to L2 (gpu scope)
    __syncthreads();      // CTA-local: W smem, bias, flag, x16 all issued
    const int is64 = *(const int*)(smem + OFF_FLAG);

    // ---- pre-stage tile-0 slot-0 A (self rows: converted by THIS CTA) --------
    const int r  = tid >> 2;               // tile row 0..127 this thread stages
    const int c0 = (tid & 3) * 4;          // first of 4 16B-chunks (of 16)
    const long long* nbr64 = (const long long*)nbr_raw;
    const int*       nbr32 = (const int*)nbr_raw;

    auto load_idxs = [&](int tile, int* dst) {
        const int grow = tile * 128 + r;
        const bool v = grow < N;
        const int base = v ? grow : 0;
        dst[0] = base;
        if (is64) {
            const long long* p = nbr64 + (size_t)base * 4;
            #pragma unroll
            for (int k = 0; k < 4; ++k) dst[k + 1] = v ? (int)p[k] : 0;
        } else {
            const int* p = nbr32 + (size_t)base * 4;
            #pragma unroll
            for (int k = 0; k < 4; ++k) dst[k + 1] = v ? p[k] : 0;
        }
    };
    auto stage_A = [&](int src_row, int buf) {
        const char* src = (const char*)g_x16 + (size_t)src_row * 256;
        const uint32_t dst = sb + OFF_A + (uint32_t)buf * 32768u;
        #pragma unroll
        for (int c = 0; c < 4; ++c) {
            const int chunk = c0 + c;
            CP_ASYNC16(dst + tile_off(r, chunk * 8), src + chunk * 16);
        }
    };

    int idxs[NSLOT], nidxs[NSLOT];
    int tile = bid;
    if (tile < ntiles) {
        load_idxs(tile, idxs);
        stage_A(idxs[0], 0);    // reads rows this CTA converted (fenced above)
    }
    CP_COMMIT();

    // ---- software grid barrier (all 148 CTAs co-resident) --------------------
    if (tid == 0) {
        const unsigned token  = atomicAdd(&g_ctr, 1u);
        const unsigned target = token - (token % GRID_CTAS) + GRID_CTAS;
        while ((int)(*(volatile unsigned*)&g_ctr - target) < 0) { }
        __threadfence();
    }
    __syncthreads();           // x16 complete chip-wide; begin GEMM

    // ======================= PHASE B: GEMM (R13 loop) ==========================
    const int wm = wid >> 2;
    const int wn = wid & 3;

    float acc[2][4][4];
    #pragma unroll
    for (int mt = 0; mt < 2; ++mt)
        #pragma unroll
        for (int nt = 0; nt < 4; ++nt)
            #pragma unroll
            for (int q = 0; q < 4; ++q) acc[mt][nt][q] = 0.0f;

    const int a_row  = (lid & 15);
    const int a_gsel = (lid >> 4);
    const int b_row  = (lid & 7);
    const int b_ntin = (lid >> 4);
    const int b_gsel = ((lid >> 3) & 1);

    const int rl = lid >> 2;
    const int cl = (lid & 3) * 2;

    int buf = 0;
    for (; tile < ntiles; tile += GRID_CTAS) {
        const int next_tile = tile + GRID_CTAS;
        #pragma unroll
        for (int j = 0; j < NSLOT; ++j) {
            if (j == 3 && next_tile < ntiles) load_idxs(next_tile, nidxs);

            asm volatile("cp.async.wait_group 0;" ::: "memory");  // A_j landed
            __syncthreads();   // all warps done with buf^1; A[buf] visible

            const bool has_next = (j < NSLOT - 1) || (next_tile < ntiles);
            if (has_next) {
                const int src_row = (j < NSLOT - 1) ? idxs[j + 1] : nidxs[0];
                stage_A(src_row, buf ^ 1);
                CP_COMMIT();
            }

            const uint32_t wbase = sb + OFF_W + (uint32_t)j * 32768u;
            const uint32_t abase = sb + OFF_A + (uint32_t)buf * 32768u;
            #pragma unroll
            for (int kc = 0; kc < 8; ++kc) {
                uint32_t bh[4][2];
                const int gB = kc * 2 + b_gsel;
                #pragma unroll
                for (int p = 0; p < 2; ++p) {
                    const int nr = wn * 32 + p * 16 + b_ntin * 8 + b_row;
                    const uint32_t off =
                        (uint32_t)nr * 256u + (((uint32_t)(gB ^ (nr & 7))) << 4);
                    uint32_t rr[4];
                    ldsm_x4(rr, wbase + off);
                    bh[p * 2 + 0][0] = rr[0];
                    bh[p * 2 + 0][1] = rr[1];
                    bh[p * 2 + 1][0] = rr[2];
                    bh[p * 2 + 1][1] = rr[3];
                }
                const int gA = kc * 2 + a_gsel;
                #pragma unroll
                for (int mt = 0; mt < 2; ++mt) {
                    const int ar = wm * 32 + mt * 16 + a_row;
                    const uint32_t off =
                        (uint32_t)ar * 256u + (((uint32_t)(gA ^ (ar & 7))) << 4);
                    uint32_t ah[4];
                    ldsm_x4(ah, abase + off);
                    #pragma unroll
                    for (int nt = 0; nt < 4; ++nt)
                        mma16816(acc[mt][nt], ah, bh[nt]);
                }
            }
            buf ^= 1;
        }

        // ---- epilogue (bias from smem; overlaps next tile's slot-0 staging) ----
        const int row0 = tile * 128;
        const float* bs = (const float*)(smem + OFF_BIAS);
        #pragma unroll
        for (int mt = 0; mt < 2; ++mt) {
            const int r_base = row0 + wm * 32 + mt * 16 + rl;
            #pragma unroll
            for (int nt = 0; nt < 4; ++nt) {
                const int col = wn * 32 + nt * 8 + cl;
                const float b0 = bs[col], b1 = bs[col + 1];
                if (r_base < N) {
                    float2 vv = make_float2(acc[mt][nt][0] + b0,
                                            acc[mt][nt][1] + b1);
                    *(float2*)(out + (size_t)r_base * 128 + col) = vv;
                }
                if (r_base + 8 < N) {
                    float2 vv = make_float2(acc[mt][nt][2] + b0,
                                            acc[mt][nt][3] + b1);
                    *(float2*)(out + (size_t)(r_base + 8) * 128 + col) = vv;
                }
                #pragma unroll
                for (int q = 0; q < 4; ++q) acc[mt][nt][q] = 0.0f;
            }
        }

        #pragma unroll
        for (int k = 0; k < NSLOT; ++k) idxs[k] = nidxs[k];
    }
}

// ---- launch ------------------------------------------------------------------
extern "C" void kernel_launch(void* const* d_in, const int* in_sizes, int n_in,
                              void* d_out, int out_size) {
    const float* x   = (const float*)d_in[0];
    const void*  nbr = d_in[1];
    const float* W   = (const float*)d_in[2];
    const float* b   = (const float*)d_in[3];
    float* out = (float*)d_out;
    const int N = in_sizes[0] / 128;

    cudaFuncSetAttribute(mcconv_kernel,
                         cudaFuncAttributeMaxDynamicSharedMemorySize, SMEM_BYTES);

    mcconv_kernel<<<GRID_CTAS, 512, SMEM_BYTES>>>(x, nbr, W, b, out, N);
}

// round 15
// speedup vs baseline: 1.0268x; 1.0268x over previous
#include <cuda_runtime.h>
#include <cuda_fp16.h>
#include <cstdint>

// ============================================================================
// MotherCubeConv: y[n] = concat(x[n], x[nbr0..3(n)]) @ W^T + b
//   N=200000, F_in=128, fan_in=640, F_out=128.
// fp16 mma.sync. R15 = R13 (best GEMM loop) with:
//   - W fp32->fp16 converted in-kernel straight into resident SMEM (no g_Wh)
//   - parallel nbr-dtype detect (64 threads + smem atomicOr)
//   - prep kernel reduced to pure x conversion, __ldcs on dead fp32 reads
// Persistent CTAs, one barrier per slot, A double-buffered cp.async gather.
// ============================================================================

#define NSLOT 5
#define MAX_ROWS 200704
#define GRID_CTAS 148

// ---- scratch (__device__ globals; no allocation allowed) -------------------
__device__ uint4 g_x16[(size_t)MAX_ROWS * 16];  // fp16 image of x (51.4MB)

// ---- helpers ----------------------------------------------------------------
__device__ __forceinline__ uint32_t smem_u32(const void* p) {
    uint32_t a;
    asm("{ .reg .u64 t; cvta.to.shared.u64 t, %1; cvt.u32.u64 %0, t; }"
        : "=r"(a) : "l"(p));
    return a;
}

__device__ __forceinline__ void ldsm_x4(uint32_t* r, uint32_t addr) {
    asm volatile("ldmatrix.sync.aligned.m8n8.x4.shared.b16 {%0,%1,%2,%3}, [%4];"
                 : "=r"(r[0]), "=r"(r[1]), "=r"(r[2]), "=r"(r[3]) : "r"(addr));
}

__device__ __forceinline__ void mma16816(float* d, const uint32_t* a,
                                         const uint32_t* b) {
    asm volatile(
        "mma.sync.aligned.m16n8k16.row.col.f32.f16.f16.f32 "
        "{%0,%1,%2,%3}, {%4,%5,%6,%7}, {%8,%9}, {%0,%1,%2,%3};"
        : "+f"(d[0]), "+f"(d[1]), "+f"(d[2]), "+f"(d[3])
        : "r"(a[0]), "r"(a[1]), "r"(a[2]), "r"(a[3]), "r"(b[0]), "r"(b[1]));
}

#define CP_ASYNC16(dst, src) \
    asm volatile("cp.async.cg.shared.global [%0], [%1], 16;" \
                 :: "r"(dst), "l"(src) : "memory")
#define CP_COMMIT() asm volatile("cp.async.commit_group;" ::: "memory")

// Swizzled byte offset: 256B row stride (16 groups of 16B), group XOR row&7.
__device__ __forceinline__ uint32_t tile_off(int row, int k) {
    uint32_t g = (uint32_t)(k >> 3);
    return (uint32_t)row * 256u + (((g ^ (uint32_t)(row & 7)) << 4)) +
           (uint32_t)(k & 7) * 2u;
}

// ---- prep: x (fp32) -> g_x16 (fp16), evict-first source reads ---------------
__global__ void cvt_x_kernel(const float* __restrict__ x, int ngroups) {
    const int t = blockIdx.x * blockDim.x + threadIdx.x;
    if (t >= ngroups) return;
    const float4* s = (const float4*)x + (size_t)t * 2;
    float4 a = __ldcs(s);          // dead after conversion: don't pollute L2
    float4 b = __ldcs(s + 1);
    __half2 h0 = __floats2half2_rn(a.x, a.y);
    __half2 h1 = __floats2half2_rn(a.z, a.w);
    __half2 h2 = __floats2half2_rn(b.x, b.y);
    __half2 h3 = __floats2half2_rn(b.z, b.w);
    uint4 u;
    u.x = *(uint32_t*)&h0; u.y = *(uint32_t*)&h1;
    u.z = *(uint32_t*)&h2; u.w = *(uint32_t*)&h3;
    g_x16[t] = u;
}

// ---- SMEM layout --------------------------------------------------------------
static constexpr uint32_t OFF_BIAS = 0;        // 512B (128 f32)
static constexpr uint32_t OFF_FLAG = 512;      // int: any nonzero hi word
static constexpr uint32_t OFF_W    = 1024;     // 5 x 32KB (resident)
static constexpr uint32_t OFF_A    = 164864;   // 2 x 32KB
static constexpr uint32_t SMEM_BYTES = 230400;

__global__ void __launch_bounds__(512, 1)
mcconv_kernel(const void* __restrict__ nbr_raw, const float* __restrict__ Wg,
              const float* __restrict__ bias_g, float* __restrict__ out, int N) {
    extern __shared__ char smem[];
    const uint32_t sb = smem_u32(smem);
    const int tid = threadIdx.x;
    const int wid = tid >> 5;
    const int lid = tid & 31;
    const int ntiles = (N + 127) >> 7;

    // ---- prologue: bias, dtype detect, W fp32->fp16 into resident SMEM -------
    if (tid < 128) ((float*)(smem + OFF_BIAS))[tid] = bias_g[tid];
    if (tid == 0) *(int*)(smem + OFF_FLAG) = 0;
    __syncthreads();
    if (tid < 64) {
        // int64 indices < 2^31 => all high words zero; any nonzero => int32 data
        const int hi = ((const int*)nbr_raw)[2 * tid + 1];
        if (hi != 0) atomicOr((int*)(smem + OFF_FLAG), 1);
    }
    #pragma unroll 4
    for (int i = tid; i < NSLOT * 128 * 64; i += 512) {
        const int cp = i & 63;
        const int f  = (i >> 6) & 127;
        const int j  = i >> 13;
        const float2 w = *(const float2*)(Wg + f * 640 + j * 128 + 2 * cp);
        __half2 h = __floats2half2_rn(w.x, w.y);
        *(uint32_t*)(smem + OFF_W + (uint32_t)j * 32768u + tile_off(f, 2 * cp)) =
            *(uint32_t*)&h;
    }
    __syncthreads();   // flag + W smem visible
    const int is64 = (*(const int*)(smem + OFF_FLAG)) == 0;

    // ---- gather thread assignment: 4 threads per row --------------------------
    const int r  = tid >> 2;            // tile row 0..127 this thread stages
    const int c0 = (tid & 3) * 4;       // first of 4 16B-chunks (of 16)
    const long long* nbr64 = (const long long*)nbr_raw;
    const int*       nbr32 = (const int*)nbr_raw;

    auto load_idxs = [&](int tile, int* dst) {
        const int grow = tile * 128 + r;
        const bool v = grow < N;
        const int base = v ? grow : 0;
        dst[0] = base;
        if (is64) {
            const long long* p = nbr64 + (size_t)base * 4;
            #pragma unroll
            for (int k = 0; k < 4; ++k) dst[k + 1] = v ? (int)p[k] : 0;
        } else {
            const int* p = nbr32 + (size_t)base * 4;
            #pragma unroll
            for (int k = 0; k < 4; ++k) dst[k + 1] = v ? p[k] : 0;
        }
    };
    auto stage_A = [&](int src_row, int buf) {
        const char* src = (const char*)g_x16 + (size_t)src_row * 256;
        const uint32_t dst = sb + OFF_A + (uint32_t)buf * 32768u;
        #pragma unroll
        for (int c = 0; c < 4; ++c) {
            const int chunk = c0 + c;
            CP_ASYNC16(dst + tile_off(r, chunk * 8), src + chunk * 16);
        }
    };

    int idxs[NSLOT], nidxs[NSLOT];
    int tile = blockIdx.x;
    if (tile < ntiles) {
        load_idxs(tile, idxs);
        stage_A(idxs[0], 0);
    }
    CP_COMMIT();   // group: A(tile0, slot0)

    // warp tiling: 4 (M) x 4 (N); warp tile = 32 rows x 32 cols
    const int wm = wid >> 2;
    const int wn = wid & 3;

    float acc[2][4][4];
    #pragma unroll
    for (int mt = 0; mt < 2; ++mt)
        #pragma unroll
        for (int nt = 0; nt < 4; ++nt)
            #pragma unroll
            for (int q = 0; q < 4; ++q) acc[mt][nt][q] = 0.0f;

    const int a_row  = (lid & 15);
    const int a_gsel = (lid >> 4);
    const int b_row  = (lid & 7);
    const int b_ntin = (lid >> 4);        // which nt within a pair
    const int b_gsel = ((lid >> 3) & 1);  // k-group select

    const int rl = lid >> 2;
    const int cl = (lid & 3) * 2;

    int buf = 0;
    for (; tile < ntiles; tile += GRID_CTAS) {
        const int next_tile = tile + GRID_CTAS;
        #pragma unroll
        for (int j = 0; j < NSLOT; ++j) {
            // prefetch next tile's indices mid-stream
            if (j == 3 && next_tile < ntiles) load_idxs(next_tile, nidxs);

            asm volatile("cp.async.wait_group 0;" ::: "memory");  // A_j landed
            __syncthreads();   // all warps done with buf^1; A[buf] visible

            // stage next slot into buf^1 — overlaps this slot's MMA phase
            const bool has_next = (j < NSLOT - 1) || (next_tile < ntiles);
            if (has_next) {
                const int src_row = (j < NSLOT - 1) ? idxs[j + 1] : nidxs[0];
                stage_A(src_row, buf ^ 1);
                CP_COMMIT();
            }

            const uint32_t wbase = sb + OFF_W + (uint32_t)j * 32768u;
            const uint32_t abase = sb + OFF_A + (uint32_t)buf * 32768u;
            #pragma unroll
            for (int kc = 0; kc < 8; ++kc) {
                // B frags: two x4 loads cover nt pairs {0,1},{2,3}
                uint32_t bh[4][2];
                const int gB = kc * 2 + b_gsel;
                #pragma unroll
                for (int p = 0; p < 2; ++p) {
                    const int nr = wn * 32 + p * 16 + b_ntin * 8 + b_row;
                    const uint32_t off =
                        (uint32_t)nr * 256u + (((uint32_t)(gB ^ (nr & 7))) << 4);
                    uint32_t rr[4];
                    ldsm_x4(rr, wbase + off);
                    bh[p * 2 + 0][0] = rr[0];
                    bh[p * 2 + 0][1] = rr[1];
                    bh[p * 2 + 1][0] = rr[2];
                    bh[p * 2 + 1][1] = rr[3];
                }
                // A frags: one x4 per mt (2 m-tiles of 16 rows)
                const int gA = kc * 2 + a_gsel;
                #pragma unroll
                for (int mt = 0; mt < 2; ++mt) {
                    const int ar = wm * 32 + mt * 16 + a_row;
                    const uint32_t off =
                        (uint32_t)ar * 256u + (((uint32_t)(gA ^ (ar & 7))) << 4);
                    uint32_t ah[4];
                    ldsm_x4(ah, abase + off);
                    #pragma unroll
                    for (int nt = 0; nt < 4; ++nt)
                        mma16816(acc[mt][nt], ah, bh[nt]);
                }
            }
            buf ^= 1;
        }

        // ---- epilogue (bias from smem; overlaps next tile's slot-0 staging) ----
        const int row0 = tile * 128;
        const float* bs = (const float*)(smem + OFF_BIAS);
        #pragma unroll
        for (int mt = 0; mt < 2; ++mt) {
            const int r_base = row0 + wm * 32 + mt * 16 + rl;
            #pragma unroll
            for (int nt = 0; nt < 4; ++nt) {
                const int col = wn * 32 + nt * 8 + cl;
                const float b0 = bs[col], b1 = bs[col + 1];
                if (r_base < N) {
                    float2 vv = make_float2(acc[mt][nt][0] + b0,
                                            acc[mt][nt][1] + b1);
                    *(float2*)(out + (size_t)r_base * 128 + col) = vv;
                }
                if (r_base + 8 < N) {
                    float2 vv = make_float2(acc[mt][nt][2] + b0,
                                            acc[mt][nt][3] + b1);
                    *(float2*)(out + (size_t)(r_base + 8) * 128 + col) = vv;
                }
                #pragma unroll
                for (int q = 0; q < 4; ++q) acc[mt][nt][q] = 0.0f;
            }
        }

        // roll prefetched indices
        #pragma unroll
        for (int k = 0; k < NSLOT; ++k) idxs[k] = nidxs[k];
    }
}

// ---- launch ------------------------------------------------------------------
extern "C" void kernel_launch(void* const* d_in, const int* in_sizes, int n_in,
                              void* d_out, int out_size) {
    const float* x   = (const float*)d_in[0];
    const void*  nbr = d_in[1];
    const float* W   = (const float*)d_in[2];
    const float* b   = (const float*)d_in[3];
    float* out = (float*)d_out;
    const int N = in_sizes[0] / 128;
    const int ngroups = N * 16;   // 8 fp32 elems per group

    cudaFuncSetAttribute(mcconv_kernel,
                         cudaFuncAttributeMaxDynamicSharedMemorySize, SMEM_BYTES);

    cvt_x_kernel<<<(ngroups + 255) / 256, 256>>>(x, ngroups);
    mcconv_kernel<<<GRID_CTAS, 512, SMEM_BYTES>>>(nbr, W, b, out, N);
}

// round 16
// speedup vs baseline: 1.1548x; 1.1246x over previous
#include <cuda_runtime.h>
#include <cuda_fp16.h>
#include <cstdint>

// ============================================================================
// MotherCubeConv: y[n] = concat(x[n], x[nbr0..3(n)]) @ W^T + b
//   N=200000, F_in=128, fan_in=640, F_out=128.
// fp16 mma.sync. R16 = R13 with the CTA split into two independent 256-thread
// halves (rows 0-63 / 64-127): per-half A double-buffers + named 256-wide
// bar.sync per slot (ids 1/2) instead of one 512-wide __syncthreads. W
// resident & shared read-only. Prep kernel: x fp32->fp16 image (DRAM floor).
// ============================================================================

#define NSLOT 5
#define MAX_ROWS 200704
#define GRID_CTAS 148

// ---- scratch (__device__ globals; no allocation allowed) -------------------
__device__ uint4 g_Wh[NSLOT * 2048];            // 5 x [128x128] fp16, swizzled
__device__ uint4 g_x16[(size_t)MAX_ROWS * 16];  // fp16 image of x (51.4MB)
__device__ int   g_is64;

// ---- helpers ----------------------------------------------------------------
__device__ __forceinline__ uint32_t smem_u32(const void* p) {
    uint32_t a;
    asm("{ .reg .u64 t; cvta.to.shared.u64 t, %1; cvt.u32.u64 %0, t; }"
        : "=r"(a) : "l"(p));
    return a;
}

__device__ __forceinline__ void ldsm_x4(uint32_t* r, uint32_t addr) {
    asm volatile("ldmatrix.sync.aligned.m8n8.x4.shared.b16 {%0,%1,%2,%3}, [%4];"
                 : "=r"(r[0]), "=r"(r[1]), "=r"(r[2]), "=r"(r[3]) : "r"(addr));
}

__device__ __forceinline__ void mma16816(float* d, const uint32_t* a,
                                         const uint32_t* b) {
    asm volatile(
        "mma.sync.aligned.m16n8k16.row.col.f32.f16.f16.f32 "
        "{%0,%1,%2,%3}, {%4,%5,%6,%7}, {%8,%9}, {%0,%1,%2,%3};"
        : "+f"(d[0]), "+f"(d[1]), "+f"(d[2]), "+f"(d[3])
        : "r"(a[0]), "r"(a[1]), "r"(a[2]), "r"(a[3]), "r"(b[0]), "r"(b[1]));
}

#define CP_ASYNC16(dst, src) \
    asm volatile("cp.async.cg.shared.global [%0], [%1], 16;" \
                 :: "r"(dst), "l"(src) : "memory")
#define CP_COMMIT() asm volatile("cp.async.commit_group;" ::: "memory")
#define BAR_HALF(id) \
    asm volatile("bar.sync %0, 256;" :: "r"(id) : "memory")

// Swizzled byte offset: 256B row stride (16 groups of 16B), group XOR row&7.
__device__ __host__ __forceinline__ uint32_t tile_off(int row, int k) {
    uint32_t g = (uint32_t)(k >> 3);
    return (uint32_t)row * 256u + (((g ^ (uint32_t)(row & 7)) << 4)) +
           (uint32_t)(k & 7) * 2u;
}

// ---- prep: x fp32 -> fp16 image, W -> fp16 swizzled, dtype detect -----------
__global__ void prep_kernel(const float* __restrict__ x,
                            const float* __restrict__ W,
                            const int* __restrict__ nbr, int ngroups) {
    const int t = blockIdx.x * blockDim.x + threadIdx.x;
    if (t < ngroups) {
        const float4* s = (const float4*)x + (size_t)t * 2;
        float4 a = __ldcs(s);      // fp32 x is dead after conversion
        float4 b = __ldcs(s + 1);
        __half2 h0 = __floats2half2_rn(a.x, a.y);
        __half2 h1 = __floats2half2_rn(a.z, a.w);
        __half2 h2 = __floats2half2_rn(b.x, b.y);
        __half2 h3 = __floats2half2_rn(b.z, b.w);
        uint4 u;
        u.x = *(uint32_t*)&h0; u.y = *(uint32_t*)&h1;
        u.z = *(uint32_t*)&h2; u.w = *(uint32_t*)&h3;
        g_x16[t] = u;
    }
    if (t < NSLOT * 128 * 64) {
        int cp = t & 63;
        int f  = (t >> 6) & 127;
        int j  = t >> 13;
        int k  = cp * 2;
        __half2 h = __floats2half2_rn(W[f * 640 + j * 128 + k],
                                      W[f * 640 + j * 128 + k + 1]);
        *(uint32_t*)((char*)g_Wh + (size_t)j * 32768 + tile_off(f, k)) =
            *(uint32_t*)&h;
    }
    if (t < 64) {
        // any nonzero high word => data is int32 (not wide int64)
        if (nbr[2 * t + 1] != 0) g_is64 = 0;
    }
    if (t == 64) g_is64 = 1;   // default; racing writes resolve: the 0-writes
                               // only fire when data is int32 (hi words != 0),
                               // and then at least one 0 lands after/with the 1
}

// ---- SMEM layout --------------------------------------------------------------
static constexpr uint32_t OFF_BIAS = 0;        // 512B
static constexpr uint32_t OFF_W    = 1024;     // 5 x 32KB (resident)
static constexpr uint32_t OFF_A    = 164864;   // 4 x 16KB: [h0b0,h0b1,h1b0,h1b1]
static constexpr uint32_t SMEM_BYTES = 230400;

__global__ void __launch_bounds__(512, 1)
mcconv_kernel(const void* __restrict__ nbr_raw,
              const float* __restrict__ bias_g, float* __restrict__ out, int N) {
    extern __shared__ char smem[];
    const uint32_t sb = smem_u32(smem);
    const int tid = threadIdx.x;
    const int wid = tid >> 5;
    const int lid = tid & 31;
    const int ntiles = (N + 127) >> 7;

    if (tid < 128) ((float*)(smem + OFF_BIAS))[tid] = bias_g[tid];

    // ---- stage all W (160KB) once (full CTA, one group) -----------------------
    {
        const char* src = (const char*)g_Wh;
        const uint32_t dst = sb + OFF_W;
        #pragma unroll
        for (int w = 0; w < 20; ++w) {
            const uint32_t e = (uint32_t)(tid + w * 512) * 16u;
            CP_ASYNC16(dst + e, src + e);
        }
    }

    // ---- half decomposition ----------------------------------------------------
    const int h     = tid >> 8;          // 0 / 1
    const int htid  = tid & 255;
    const int barid = h + 1;             // named barrier ids 1,2
    const int rloc  = htid >> 2;         // local row 0..63 this thread stages
    const int c0    = (htid & 3) * 4;    // first of 4 16B-chunks (of 16)
    const int is64  = g_is64;
    const long long* nbr64 = (const long long*)nbr_raw;
    const int*       nbr32 = (const int*)nbr_raw;

    auto load_idxs = [&](int tile, int* dst) {
        const int grow = tile * 128 + h * 64 + rloc;
        const bool v = grow < N;
        const int base = v ? grow : 0;
        dst[0] = base;
        if (is64) {
            const long long* p = nbr64 + (size_t)base * 4;
            #pragma unroll
            for (int k = 0; k < 4; ++k) dst[k + 1] = v ? (int)p[k] : 0;
        } else {
            const int* p = nbr32 + (size_t)base * 4;
            #pragma unroll
            for (int k = 0; k < 4; ++k) dst[k + 1] = v ? p[k] : 0;
        }
    };
    auto stage_A = [&](int src_row, int buf) {
        const char* src = (const char*)g_x16 + (size_t)src_row * 256;
        const uint32_t dst =
            sb + OFF_A + (uint32_t)(h * 2 + buf) * 16384u;
        #pragma unroll
        for (int c = 0; c < 4; ++c) {
            const int chunk = c0 + c;
            CP_ASYNC16(dst + tile_off(rloc, chunk * 8), src + chunk * 16);
        }
    };

    int idxs[NSLOT], nidxs[NSLOT];
    int tile = blockIdx.x;
    if (tile < ntiles) {
        load_idxs(tile, idxs);
        stage_A(idxs[0], 0);
    }
    CP_COMMIT();   // group: W + A(tile0, slot0)

    __syncthreads();   // bias visible to both halves before loop

    // warp tiling within half: 2 (M) x 4 (N); warp tile 32x32
    const int wm = (wid >> 2) & 1;       // m-half within this half's 64 rows
    const int wn = wid & 3;

    float acc[2][4][4];
    #pragma unroll
    for (int mt = 0; mt < 2; ++mt)
        #pragma unroll
        for (int nt = 0; nt < 4; ++nt)
            #pragma unroll
            for (int q = 0; q < 4; ++q) acc[mt][nt][q] = 0.0f;

    const int a_row  = (lid & 15);
    const int a_gsel = (lid >> 4);
    const int b_row  = (lid & 7);
    const int b_ntin = (lid >> 4);        // which nt within a pair
    const int b_gsel = ((lid >> 3) & 1);  // k-group select

    const int rl = lid >> 2;
    const int cl = (lid & 3) * 2;

    int buf = 0;
    for (; tile < ntiles; tile += GRID_CTAS) {
        const int next_tile = tile + GRID_CTAS;
        #pragma unroll
        for (int j = 0; j < NSLOT; ++j) {
            if (j == 3 && next_tile < ntiles) load_idxs(next_tile, nidxs);

            asm volatile("cp.async.wait_group 0;" ::: "memory");  // A_j landed
            BAR_HALF(barid);   // this half done with buf^1; A[buf] visible

            const bool has_next = (j < NSLOT - 1) || (next_tile < ntiles);
            if (has_next) {
                const int src_row = (j < NSLOT - 1) ? idxs[j + 1] : nidxs[0];
                stage_A(src_row, buf ^ 1);
                CP_COMMIT();
            }

            const uint32_t wbase = sb + OFF_W + (uint32_t)j * 32768u;
            const uint32_t abase =
                sb + OFF_A + (uint32_t)(h * 2 + buf) * 16384u;
            #pragma unroll
            for (int kc = 0; kc < 8; ++kc) {
                // B frags: two x4 loads cover nt pairs {0,1},{2,3}
                uint32_t bh[4][2];
                const int gB = kc * 2 + b_gsel;
                #pragma unroll
                for (int p = 0; p < 2; ++p) {
                    const int nr = wn * 32 + p * 16 + b_ntin * 8 + b_row;
                    const uint32_t off =
                        (uint32_t)nr * 256u + (((uint32_t)(gB ^ (nr & 7))) << 4);
                    uint32_t rr[4];
                    ldsm_x4(rr, wbase + off);
                    bh[p * 2 + 0][0] = rr[0];
                    bh[p * 2 + 0][1] = rr[1];
                    bh[p * 2 + 1][0] = rr[2];
                    bh[p * 2 + 1][1] = rr[3];
                }
                // A frags: one x4 per mt, from this half's buffer
                const int gA = kc * 2 + a_gsel;
                #pragma unroll
                for (int mt = 0; mt < 2; ++mt) {
                    const int ar = wm * 32 + mt * 16 + a_row;
                    const uint32_t off =
                        (uint32_t)ar * 256u + (((uint32_t)(gA ^ (ar & 7))) << 4);
                    uint32_t ah[4];
                    ldsm_x4(ah, abase + off);
                    #pragma unroll
                    for (int nt = 0; nt < 4; ++nt)
                        mma16816(acc[mt][nt], ah, bh[nt]);
                }
            }
            buf ^= 1;
        }

        // ---- epilogue (bias from smem; next tile's slot-0 already in flight) ---
        const int row0 = tile * 128 + h * 64;
        const float* bs = (const float*)(smem + OFF_BIAS);
        #pragma unroll
        for (int mt = 0; mt < 2; ++mt) {
            const int r_base = row0 + wm * 32 + mt * 16 + rl;
            #pragma unroll
            for (int nt = 0; nt < 4; ++nt) {
                const int col = wn * 32 + nt * 8 + cl;
                const float b0 = bs[col], b1 = bs[col + 1];
                if (r_base < N) {
                    float2 vv = make_float2(acc[mt][nt][0] + b0,
                                            acc[mt][nt][1] + b1);
                    *(float2*)(out + (size_t)r_base * 128 + col) = vv;
                }
                if (r_base + 8 < N) {
                    float2 vv = make_float2(acc[mt][nt][2] + b0,
                                            acc[mt][nt][3] + b1);
                    *(float2*)(out + (size_t)(r_base + 8) * 128 + col) = vv;
                }
                #pragma unroll
                for (int q = 0; q < 4; ++q) acc[mt][nt][q] = 0.0f;
            }
        }

        #pragma unroll
        for (int k = 0; k < NSLOT; ++k) idxs[k] = nidxs[k];
    }
}

// ---- launch ------------------------------------------------------------------
extern "C" void kernel_launch(void* const* d_in, const int* in_sizes, int n_in,
                              void* d_out, int out_size) {
    const float* x   = (const float*)d_in[0];
    const void*  nbr = d_in[1];
    const float* W   = (const float*)d_in[2];
    const float* b   = (const float*)d_in[3];
    float* out = (float*)d_out;
    const int N = in_sizes[0] / 128;
    const int ngroups = N * 16;   // 8 fp32 elems per group

    cudaFuncSetAttribute(mcconv_kernel,
                         cudaFuncAttributeMaxDynamicSharedMemorySize, SMEM_BYTES);

    prep_kernel<<<(ngroups + 255) / 256, 256>>>(x, W, (const int*)nbr, ngroups);
    mcconv_kernel<<<GRID_CTAS, 512, SMEM_BYTES>>>(nbr, b, out, N);
}